// round 7
// baseline (speedup 1.0000x reference)
#include <cuda_runtime.h>

#define NB 4
#define NT 16384
#define NCOND 80
#define NLAY 40
#define TT 472
#define HALO 40
#define TTH 512
#define TILES_PER_B 35
#define NTHREADS 512

// transposed, pair-duplicated weight offsets (floats) within wd
#define D0T 0       // dil k=0 taps: [i][c] dup -> 2048
#define D1T 2048    // dil k=1 taps
#define F2T 4096    // f  [k][c] dup -> 2048
#define G2T 6144
#define CF2T 8192   // cf [k][c] dup -> 5120
#define CG2T 13312
#define O2T 18432
#define WTOT 20480

#define SMEM_FLOATS (32*TTH + 32*TTH + WTOT + 32)
#define SMEM_BYTES  (SMEM_FLOATS * 4)

typedef unsigned long long u64;

__device__ __forceinline__ u64 pk(float lo, float hi) {
    u64 r; asm("mov.b64 %0,{%1,%2};" : "=l"(r) : "f"(lo), "f"(hi)); return r;
}
__device__ __forceinline__ void upk(u64 v, float& a, float& b) {
    asm("mov.b64 {%0,%1},%2;" : "=f"(a), "=f"(b) : "l"(v));
}
__device__ __forceinline__ u64 fma2(u64 a, u64 b, u64 c) {
    u64 d; asm("fma.rn.f32x2 %0,%1,%2,%3;" : "=l"(d) : "l"(a), "l"(b), "l"(c)); return d;
}
__device__ __forceinline__ u64 add2(u64 a, u64 b) {
    u64 d; asm("add.rn.f32x2 %0,%1,%2;" : "=l"(d) : "l"(a), "l"(b)); return d;
}
__device__ __forceinline__ float fast_sigmoid(float v) {
    v = fminf(fmaxf(v, -30.f), 30.f);
    return __fdividef(1.f, 1.f + __expf(-v));
}
__device__ __forceinline__ float fast_tanh(float v) {
    v = fminf(fmaxf(v, -15.f), 15.f);
    float e2 = __expf(2.f * v);
    return __fdividef(e2 - 1.f, e2 + 1.f);
}

__global__ void __launch_bounds__(NTHREADS, 1)
wavenet_kernel(const float* __restrict__ x, const float* __restrict__ h,
               const float* __restrict__ start_w, const float* __restrict__ dil_w,
               const float* __restrict__ f_w, const float* __restrict__ g_w,
               const float* __restrict__ cf_w, const float* __restrict__ cg_w,
               const float* __restrict__ out_w, const float* __restrict__ end1_w,
               const float* __restrict__ end2_w, float* __restrict__ out)
{
    extern __shared__ float smem[];
    float* res  = smem;               // [32][TTH]
    float* ybuf = smem + 32 * TTH;    // [32][TTH]
    float* wd   = smem + 64 * TTH;    // [WTOT]
    float* sw   = wd + WTOT;          // [32]

    const int tid = threadIdx.x;
    const int b   = blockIdx.x / TILES_PER_B;
    const int tc  = blockIdx.x % TILES_PER_B;
    const int tgb = tc * TT - HALO;

    if (tid < 32) sw[tid] = start_w[tid];
    for (int idx = tid; idx < 32 * TTH; idx += NTHREADS) {
        int ch = idx >> 9, lt = idx & (TTH - 1);
        int tg = tgb + lt;
        float xv = (tg >= 0 && tg < NT) ? x[b * NT + tg] : 0.f;
        res[idx] = start_w[ch] * xv;
    }
    __syncthreads();

    // ---- layer-loop tiling: thread = 8 ch x 4 t, lanes contiguous in time ----
    const int c0  = (tid >> 7) * 8;        // 0,8,16,24
    const int lt0 = (tid & 127) * 4;       // 0..508, lane-contiguous
    const int tg0 = tgb + lt0;
    const bool hval = (tg0 >= 0 && tg0 + 4 <= NT);
    const float* hb = h + ((size_t)(b * NCOND)) * NT + tg0;

    for (int l = 0; l < NLAY; ++l) {
        // ---- stage weights: transposed [k][c], duplicated (w,w) ----
        {
            const float* dl = dil_w + l * 2048;
            for (int j = tid; j < 1024; j += NTHREADS) {
                int c = j >> 5, i = j & 31;
                float2 w = *(const float2*)(dl + 2 * j);
                int d = (i * 32 + c) * 2;
                *(float2*)(wd + D0T + d) = make_float2(w.x, w.x);
                *(float2*)(wd + D1T + d) = make_float2(w.y, w.y);
            }
            const float* fl = f_w + l * 1024;
            const float* gl = g_w + l * 1024;
            for (int j = tid; j < 1024; j += NTHREADS) {
                int c = j >> 5, k = j & 31;
                int d = (k * 32 + c) * 2;
                float vf = fl[j], vg = gl[j];
                *(float2*)(wd + F2T + d) = make_float2(vf, vf);
                *(float2*)(wd + G2T + d) = make_float2(vg, vg);
            }
            const float* cfl = cf_w + l * 2560;
            const float* cgl = cg_w + l * 2560;
            for (int j = tid; j < 2560; j += NTHREADS) {
                int c = j / 80, k = j - c * 80;
                int d = (k * 32 + c) * 2;
                float vf = cfl[j], vg = cgl[j];
                *(float2*)(wd + CF2T + d) = make_float2(vf, vf);
                *(float2*)(wd + CG2T + d) = make_float2(vg, vg);
            }
            const float* ol = out_w + l * 1024;
            for (int j = tid; j < 1024; j += NTHREADS) {
                int c = j >> 5, k = j & 31;
                float v = ol[j];
                *(float2*)(wd + O2T + (k * 32 + c) * 2) = make_float2(v, v);
            }
        }
        __syncthreads();

        // ---- G1: y[c,t] = W0[c,i]*res[i,t-1] + W1[c,i]*res[i,t] ----
        {
            u64 acc[8][2];
            #pragma unroll
            for (int a = 0; a < 8; ++a) { acc[a][0] = 0ULL; acc[a][1] = 0ULL; }

            #pragma unroll 2
            for (int i = 0; i < 32; ++i) {
                const float* rr = res + i * TTH + lt0;
                ulonglong2 cc_ = *(const ulonglong2*)rr;          // (r0,r1)(r2,r3)
                u64 pv = (lt0 > 0) ? *(const u64*)(rr - 2) : 0ULL; // (r-2,r-1)
                float r0, r1, r2, r3, rm2, rm1;
                upk(cc_.x, r0, r1); upk(cc_.y, r2, r3); upk(pv, rm2, rm1);
                u64 d0 = pk(rm1, r0), d1 = pk(r1, r2);
                const float* wp0 = wd + D0T + (i * 32 + c0) * 2;
                const float* wp1 = wd + D1T + (i * 32 + c0) * 2;
                ulonglong2 w0A = *(const ulonglong2*)wp0;
                ulonglong2 w0B = *(const ulonglong2*)(wp0 + 4);
                ulonglong2 w0C = *(const ulonglong2*)(wp0 + 8);
                ulonglong2 w0D = *(const ulonglong2*)(wp0 + 12);
                ulonglong2 w1A = *(const ulonglong2*)wp1;
                ulonglong2 w1B = *(const ulonglong2*)(wp1 + 4);
                ulonglong2 w1C = *(const ulonglong2*)(wp1 + 8);
                ulonglong2 w1D = *(const ulonglong2*)(wp1 + 12);
                u64 w0_[8] = {w0A.x, w0A.y, w0B.x, w0B.y, w0C.x, w0C.y, w0D.x, w0D.y};
                u64 w1_[8] = {w1A.x, w1A.y, w1B.x, w1B.y, w1C.x, w1C.y, w1D.x, w1D.y};
                #pragma unroll
                for (int cc = 0; cc < 8; ++cc) {
                    acc[cc][0] = fma2(d0,    w0_[cc], acc[cc][0]);
                    acc[cc][0] = fma2(cc_.x, w1_[cc], acc[cc][0]);
                    acc[cc][1] = fma2(d1,    w0_[cc], acc[cc][1]);
                    acc[cc][1] = fma2(cc_.y, w1_[cc], acc[cc][1]);
                }
            }
            #pragma unroll
            for (int cc = 0; cc < 8; ++cc)
                *(ulonglong2*)(ybuf + (c0 + cc) * TTH + lt0) =
                    make_ulonglong2(acc[cc][0], acc[cc][1]);
        }
        __syncthreads();

        // ---- G2: z = tanh(F@y + CF@h) * sigmoid(G@y + CG@h) ----
        u64 zp[8][2];
        {
            u64 pf[8][2], pg[8][2];
            #pragma unroll
            for (int a = 0; a < 8; ++a) {
                pf[a][0] = 0ULL; pf[a][1] = 0ULL;
                pg[a][0] = 0ULL; pg[a][1] = 0ULL;
            }

            if (hval) {  // h-pass: batched coalesced LDG (MLP 4)
                for (int k = 0; k < NCOND; k += 4) {
                    ulonglong2 hv[4];
                    #pragma unroll
                    for (int q = 0; q < 4; ++q)
                        hv[q] = *(const ulonglong2*)(hb + (size_t)(k + q) * NT);
                    #pragma unroll
                    for (int q = 0; q < 4; ++q) {
                        const float* wfp = wd + CF2T + ((k + q) * 32 + c0) * 2;
                        const float* wgp = wd + CG2T + ((k + q) * 32 + c0) * 2;
                        ulonglong2 fA = *(const ulonglong2*)wfp;
                        ulonglong2 fB = *(const ulonglong2*)(wfp + 4);
                        ulonglong2 fC = *(const ulonglong2*)(wfp + 8);
                        ulonglong2 fD = *(const ulonglong2*)(wfp + 12);
                        ulonglong2 gA = *(const ulonglong2*)wgp;
                        ulonglong2 gB = *(const ulonglong2*)(wgp + 4);
                        ulonglong2 gC = *(const ulonglong2*)(wgp + 8);
                        ulonglong2 gD = *(const ulonglong2*)(wgp + 12);
                        u64 wf_[8] = {fA.x, fA.y, fB.x, fB.y, fC.x, fC.y, fD.x, fD.y};
                        u64 wg_[8] = {gA.x, gA.y, gB.x, gB.y, gC.x, gC.y, gD.x, gD.y};
                        #pragma unroll
                        for (int cc = 0; cc < 8; ++cc) {
                            pf[cc][0] = fma2(hv[q].x, wf_[cc], pf[cc][0]);
                            pf[cc][1] = fma2(hv[q].y, wf_[cc], pf[cc][1]);
                            pg[cc][0] = fma2(hv[q].x, wg_[cc], pg[cc][0]);
                            pg[cc][1] = fma2(hv[q].y, wg_[cc], pg[cc][1]);
                        }
                    }
                }
            }
            // y-pass
            #pragma unroll 2
            for (int k = 0; k < 32; ++k) {
                ulonglong2 yv = *(const ulonglong2*)(ybuf + k * TTH + lt0);
                const float* wfp = wd + F2T + (k * 32 + c0) * 2;
                const float* wgp = wd + G2T + (k * 32 + c0) * 2;
                ulonglong2 fA = *(const ulonglong2*)wfp;
                ulonglong2 fB = *(const ulonglong2*)(wfp + 4);
                ulonglong2 fC = *(const ulonglong2*)(wfp + 8);
                ulonglong2 fD = *(const ulonglong2*)(wfp + 12);
                ulonglong2 gA = *(const ulonglong2*)wgp;
                ulonglong2 gB = *(const ulonglong2*)(wgp + 4);
                ulonglong2 gC = *(const ulonglong2*)(wgp + 8);
                ulonglong2 gD = *(const ulonglong2*)(wgp + 12);
                u64 wf_[8] = {fA.x, fA.y, fB.x, fB.y, fC.x, fC.y, fD.x, fD.y};
                u64 wg_[8] = {gA.x, gA.y, gB.x, gB.y, gC.x, gC.y, gD.x, gD.y};
                #pragma unroll
                for (int cc = 0; cc < 8; ++cc) {
                    pf[cc][0] = fma2(yv.x, wf_[cc], pf[cc][0]);
                    pf[cc][1] = fma2(yv.y, wf_[cc], pf[cc][1]);
                    pg[cc][0] = fma2(yv.x, wg_[cc], pg[cc][0]);
                    pg[cc][1] = fma2(yv.y, wg_[cc], pg[cc][1]);
                }
            }
            #pragma unroll
            for (int cc = 0; cc < 8; ++cc)
                #pragma unroll
                for (int p = 0; p < 2; ++p) {
                    float f0, f1, g0, g1;
                    upk(pf[cc][p], f0, f1); upk(pg[cc][p], g0, g1);
                    zp[cc][p] = pk(fast_tanh(f0) * fast_sigmoid(g0),
                                   fast_tanh(f1) * fast_sigmoid(g1));
                }
        }
        __syncthreads();   // all reads of y done
        #pragma unroll
        for (int cc = 0; cc < 8; ++cc)
            *(ulonglong2*)(ybuf + (c0 + cc) * TTH + lt0) =
                make_ulonglong2(zp[cc][0], zp[cc][1]);
        __syncthreads();   // z complete

        // ---- G3: res += Ow @ z ----
        {
            u64 acc[8][2];
            #pragma unroll
            for (int a = 0; a < 8; ++a) { acc[a][0] = 0ULL; acc[a][1] = 0ULL; }

            #pragma unroll 2
            for (int k = 0; k < 32; ++k) {
                ulonglong2 zv = *(const ulonglong2*)(ybuf + k * TTH + lt0);
                const float* wp = wd + O2T + (k * 32 + c0) * 2;
                ulonglong2 wA = *(const ulonglong2*)wp;
                ulonglong2 wB = *(const ulonglong2*)(wp + 4);
                ulonglong2 wC = *(const ulonglong2*)(wp + 8);
                ulonglong2 wD = *(const ulonglong2*)(wp + 12);
                u64 w_[8] = {wA.x, wA.y, wB.x, wB.y, wC.x, wC.y, wD.x, wD.y};
                #pragma unroll
                for (int cc = 0; cc < 8; ++cc) {
                    acc[cc][0] = fma2(zv.x, w_[cc], acc[cc][0]);
                    acc[cc][1] = fma2(zv.y, w_[cc], acc[cc][1]);
                }
            }
            if (tg0 >= 0) {
                #pragma unroll
                for (int cc = 0; cc < 8; ++cc) {
                    float* rp = res + (c0 + cc) * TTH + lt0;
                    ulonglong2 rv = *(const ulonglong2*)rp;
                    *(ulonglong2*)rp = make_ulonglong2(add2(rv.x, acc[cc][0]),
                                                       add2(rv.y, acc[cc][1]));
                }
            }
        }
        __syncthreads();
    }

    // ---- relu(skip) -> ybuf; stage end1 transposed dup into wd ----
    for (int idx = tid; idx < 32 * TTH; idx += NTHREADS) {
        int ch = idx >> 9, lt = idx & (TTH - 1);
        int tg = tgb + lt;
        float xv = (tg >= 0 && tg < NT) ? x[b * NT + tg] : 0.f;
        ybuf[idx] = fmaxf(res[idx] - sw[ch] * xv, 0.f);
    }
    for (int j = tid; j < 8192; j += NTHREADS) {   // end1 [256][32] -> [k][s] dup
        int s = j >> 5, k = j & 31;
        float v = end1_w[j];
        *(float2*)(wd + (k * 256 + s) * 2) = make_float2(v, v);
    }
    __syncthreads();

    // ---- end head: chunks of 64 timesteps; ebuf[256][64] reuses res ----
    float* ebuf = res;
    const int cb2 = tid >> 3;   // 0..63
    const int tb8 = tid & 7;    // 0..7
    const int s0  = cb2 * 4;
    for (int chunk = 0; chunk < 8; ++chunk) {
        int ltc = HALO + chunk * 64 + tb8 * 8;
        bool active = (ltc < TTH);
        if (active) {  // E1: e = relu(end1 @ skip)
            u64 acc[4][4];
            #pragma unroll
            for (int a = 0; a < 4; ++a)
                #pragma unroll
                for (int p = 0; p < 4; ++p) acc[a][p] = 0ULL;
            #pragma unroll 2
            for (int k = 0; k < 32; ++k) {
                const float* yr = ybuf + k * TTH + ltc;
                ulonglong2 vA = *(const ulonglong2*)yr;
                ulonglong2 vB = *(const ulonglong2*)(yr + 4);
                const float* wp = wd + (k * 256 + s0) * 2;
                ulonglong2 wA = *(const ulonglong2*)wp;
                ulonglong2 wB = *(const ulonglong2*)(wp + 4);
                u64 yv[4] = {vA.x, vA.y, vB.x, vB.y};
                u64 w_[4] = {wA.x, wA.y, wB.x, wB.y};
                #pragma unroll
                for (int ss = 0; ss < 4; ++ss)
                    #pragma unroll
                    for (int p = 0; p < 4; ++p)
                        acc[ss][p] = fma2(yv[p], w_[ss], acc[ss][p]);
            }
            #pragma unroll
            for (int ss = 0; ss < 4; ++ss) {
                float* eo = ebuf + (s0 + ss) * 64 + tb8 * 8;
                #pragma unroll
                for (int p = 0; p < 4; ++p) {
                    float a0, a1; upk(acc[ss][p], a0, a1);
                    *(float2*)(eo + 2 * p) = make_float2(fmaxf(a0, 0.f), fmaxf(a1, 0.f));
                }
            }
        }
        __syncthreads();
        if (active) {  // E2: logit = end2 @ e
            u64 acc[4][4];
            #pragma unroll
            for (int a = 0; a < 4; ++a)
                #pragma unroll
                for (int p = 0; p < 4; ++p) acc[a][p] = 0ULL;
            #pragma unroll 4
            for (int k = 0; k < 256; ++k) {
                const float* er = ebuf + k * 64 + tb8 * 8;
                ulonglong2 vA = *(const ulonglong2*)er;
                ulonglong2 vB = *(const ulonglong2*)(er + 4);
                u64 ev[4] = {vA.x, vA.y, vB.x, vB.y};
                #pragma unroll
                for (int cc = 0; cc < 4; ++cc) {
                    float w = __ldg(end2_w + (s0 + cc) * 256 + k);
                    u64 wp2 = pk(w, w);
                    #pragma unroll
                    for (int p = 0; p < 4; ++p)
                        acc[cc][p] = fma2(ev[p], wp2, acc[cc][p]);
                }
            }
            int tgc = tgb + ltc;
            #pragma unroll
            for (int cc = 0; cc < 4; ++cc) {
                float* op = out + ((size_t)(b * 256 + s0 + cc)) * NT + tgc;
                if (tgc + 8 <= NT) {
                    #pragma unroll
                    for (int p = 0; p < 4; ++p)
                        *(u64*)(op + 2 * p) = acc[cc][p];
                } else {
                    #pragma unroll
                    for (int p = 0; p < 4; ++p) {
                        float a0, a1; upk(acc[cc][p], a0, a1);
                        if (tgc + 2 * p     < NT) op[2 * p]     = a0;
                        if (tgc + 2 * p + 1 < NT) op[2 * p + 1] = a1;
                    }
                }
            }
        }
        __syncthreads();
    }
}

extern "C" void kernel_launch(void* const* d_in, const int* in_sizes, int n_in,
                              void* d_out, int out_size) {
    const float* x       = (const float*)d_in[0];
    const float* h       = (const float*)d_in[1];
    const float* start_w = (const float*)d_in[2];
    const float* dil_w   = (const float*)d_in[3];
    const float* f_w     = (const float*)d_in[4];
    const float* g_w     = (const float*)d_in[5];
    const float* cf_w    = (const float*)d_in[6];
    const float* cg_w    = (const float*)d_in[7];
    const float* out_w   = (const float*)d_in[8];
    const float* end1_w  = (const float*)d_in[9];
    const float* end2_w  = (const float*)d_in[10];
    float* out = (float*)d_out;

    cudaFuncSetAttribute(wavenet_kernel,
                         cudaFuncAttributeMaxDynamicSharedMemorySize, SMEM_BYTES);
    wavenet_kernel<<<NB * TILES_PER_B, NTHREADS, SMEM_BYTES>>>(
        x, h, start_w, dil_w, f_w, g_w, cf_w, cg_w, out_w, end1_w, end2_w, out);
}

// round 10
// speedup vs baseline: 1.4726x; 1.4726x over previous
#include <cuda_runtime.h>

#define NB 4
#define NT 16384
#define NCOND 80
#define NLAY 40
#define TT 472
#define HALO 40
#define TTH 512
#define TILES_PER_B 35
#define NTHREADS 1024

// transposed, pair-duplicated weight offsets (floats) within wd
#define D0T 0       // dil k=0 taps: [i][c] dup -> 2048
#define D1T 2048    // dil k=1 taps
#define F2T 4096    // f  [k][c] dup -> 2048
#define G2T 6144
#define CF2T 8192   // cf [k][c] dup -> 5120
#define CG2T 13312
#define O2T 18432
#define WTOT 20480

#define SMEM_FLOATS (32*TTH + 32*TTH + WTOT + 32)
#define SMEM_BYTES  (SMEM_FLOATS * 4)

typedef unsigned long long u64;

__device__ __forceinline__ u64 pk(float lo, float hi) {
    u64 r; asm("mov.b64 %0,{%1,%2};" : "=l"(r) : "f"(lo), "f"(hi)); return r;
}
__device__ __forceinline__ void upk(u64 v, float& a, float& b) {
    asm("mov.b64 {%0,%1},%2;" : "=f"(a), "=f"(b) : "l"(v));
}
__device__ __forceinline__ u64 fma2(u64 a, u64 b, u64 c) {
    u64 d; asm("fma.rn.f32x2 %0,%1,%2,%3;" : "=l"(d) : "l"(a), "l"(b), "l"(c)); return d;
}
__device__ __forceinline__ u64 add2(u64 a, u64 b) {
    u64 d; asm("add.rn.f32x2 %0,%1,%2;" : "=l"(d) : "l"(a), "l"(b)); return d;
}
__device__ __forceinline__ float fast_sigmoid(float v) {
    v = fminf(fmaxf(v, -30.f), 30.f);
    return __fdividef(1.f, 1.f + __expf(-v));
}
__device__ __forceinline__ float fast_tanh(float v) {
    v = fminf(fmaxf(v, -15.f), 15.f);
    float e2 = __expf(2.f * v);
    return __fdividef(e2 - 1.f, e2 + 1.f);
}

__global__ void __launch_bounds__(NTHREADS, 1)
wavenet_kernel(const float* __restrict__ x, const float* __restrict__ h,
               const float* __restrict__ start_w, const float* __restrict__ dil_w,
               const float* __restrict__ f_w, const float* __restrict__ g_w,
               const float* __restrict__ cf_w, const float* __restrict__ cg_w,
               const float* __restrict__ out_w, const float* __restrict__ end1_w,
               const float* __restrict__ end2_w, float* __restrict__ out)
{
    extern __shared__ float smem[];
    float* res  = smem;               // [32][TTH]
    float* ybuf = smem + 32 * TTH;    // [32][TTH]
    float* wd   = smem + 64 * TTH;    // [WTOT]
    float* sw   = wd + WTOT;          // [32]

    const int tid = threadIdx.x;
    const int b   = blockIdx.x / TILES_PER_B;
    const int tc  = blockIdx.x % TILES_PER_B;
    const int tgb = tc * TT - HALO;

    if (tid < 32) sw[tid] = start_w[tid];
    for (int idx = tid; idx < 32 * TTH; idx += NTHREADS) {
        int ch = idx >> 9, lt = idx & (TTH - 1);
        int tg = tgb + lt;
        float xv = (tg >= 0 && tg < NT) ? x[b * NT + tg] : 0.f;
        res[idx] = start_w[ch] * xv;
    }
    __syncthreads();

    // ---- layer tiling: thread = 4 ch x 4 t, lanes contiguous in time ----
    const int c0  = (tid >> 7) * 4;        // 0,4,...,28
    const int lt0 = (tid & 127) * 4;       // 0..508, lane-contiguous (16B/lane)
    const int tg0 = tgb + lt0;
    const bool hval = (tg0 >= 0 && tg0 + 4 <= NT);
    const float* hb = h + ((size_t)(b * NCOND)) * NT + tg0;

    for (int l = 0; l < NLAY; ++l) {
        // ---- stage weights: transposed [k][c], duplicated (w,w) ----
        {
            const float* dl = dil_w + l * 2048;
            for (int j = tid; j < 1024; j += NTHREADS) {
                int c = j >> 5, i = j & 31;
                float2 w = *(const float2*)(dl + 2 * j);
                int d = (i * 32 + c) * 2;
                *(float2*)(wd + D0T + d) = make_float2(w.x, w.x);
                *(float2*)(wd + D1T + d) = make_float2(w.y, w.y);
            }
            const float* fl = f_w + l * 1024;
            const float* gl = g_w + l * 1024;
            for (int j = tid; j < 1024; j += NTHREADS) {
                int c = j >> 5, k = j & 31;
                int d = (k * 32 + c) * 2;
                float vf = fl[j], vg = gl[j];
                *(float2*)(wd + F2T + d) = make_float2(vf, vf);
                *(float2*)(wd + G2T + d) = make_float2(vg, vg);
            }
            const float* cfl = cf_w + l * 2560;
            const float* cgl = cg_w + l * 2560;
            for (int j = tid; j < 2560; j += NTHREADS) {
                int c = j / 80, k = j - c * 80;
                int d = (k * 32 + c) * 2;
                float vf = cfl[j], vg = cgl[j];
                *(float2*)(wd + CF2T + d) = make_float2(vf, vf);
                *(float2*)(wd + CG2T + d) = make_float2(vg, vg);
            }
            const float* ol = out_w + l * 1024;
            for (int j = tid; j < 1024; j += NTHREADS) {
                int c = j >> 5, k = j & 31;
                float v = ol[j];
                *(float2*)(wd + O2T + (k * 32 + c) * 2) = make_float2(v, v);
            }
        }
        __syncthreads();

        // ---- G1: y[c,t] = W0[c,i]*res[i,t-1] + W1[c,i]*res[i,t] ----
        {
            u64 acc[4][2];
            #pragma unroll
            for (int a = 0; a < 4; ++a) { acc[a][0] = 0ULL; acc[a][1] = 0ULL; }

            #pragma unroll 2
            for (int i = 0; i < 32; ++i) {
                const float* rr = res + i * TTH + lt0;
                ulonglong2 cc_ = *(const ulonglong2*)rr;           // (r0,r1)(r2,r3)
                u64 pv = (lt0 > 0) ? *(const u64*)(rr - 2) : 0ULL; // (r-2,r-1)
                float r0, r1, r2, r3, rm2, rm1;
                upk(cc_.x, r0, r1); upk(cc_.y, r2, r3); upk(pv, rm2, rm1);
                u64 d0 = pk(rm1, r0), d1 = pk(r1, r2);
                const float* wp0 = wd + D0T + (i * 32 + c0) * 2;
                const float* wp1 = wd + D1T + (i * 32 + c0) * 2;
                ulonglong2 w0A = *(const ulonglong2*)wp0;
                ulonglong2 w0B = *(const ulonglong2*)(wp0 + 4);
                ulonglong2 w1A = *(const ulonglong2*)wp1;
                ulonglong2 w1B = *(const ulonglong2*)(wp1 + 4);
                u64 w0_[4] = {w0A.x, w0A.y, w0B.x, w0B.y};
                u64 w1_[4] = {w1A.x, w1A.y, w1B.x, w1B.y};
                #pragma unroll
                for (int cc = 0; cc < 4; ++cc) {
                    acc[cc][0] = fma2(d0,    w0_[cc], acc[cc][0]);
                    acc[cc][0] = fma2(cc_.x, w1_[cc], acc[cc][0]);
                    acc[cc][1] = fma2(d1,    w0_[cc], acc[cc][1]);
                    acc[cc][1] = fma2(cc_.y, w1_[cc], acc[cc][1]);
                }
            }
            #pragma unroll
            for (int cc = 0; cc < 4; ++cc)
                *(ulonglong2*)(ybuf + (c0 + cc) * TTH + lt0) =
                    make_ulonglong2(acc[cc][0], acc[cc][1]);
        }
        __syncthreads();

        // ---- G2: z = tanh(F@y + CF@h) * sigmoid(G@y + CG@h) ----
        u64 zp[4][2];
        {
            u64 pf[4][2], pg[4][2];
            #pragma unroll
            for (int a = 0; a < 4; ++a) {
                pf[a][0] = 0ULL; pf[a][1] = 0ULL;
                pg[a][0] = 0ULL; pg[a][1] = 0ULL;
            }

            if (hval) {  // h-pass: batched coalesced LDG (MLP 2)
                #pragma unroll 1
                for (int k = 0; k < NCOND; k += 2) {
                    ulonglong2 h0 = *(const ulonglong2*)(hb + (size_t)k * NT);
                    ulonglong2 h1 = *(const ulonglong2*)(hb + (size_t)(k + 1) * NT);
                    #pragma unroll
                    for (int q = 0; q < 2; ++q) {
                        ulonglong2 hv = q ? h1 : h0;
                        const float* wfp = wd + CF2T + ((k + q) * 32 + c0) * 2;
                        const float* wgp = wd + CG2T + ((k + q) * 32 + c0) * 2;
                        ulonglong2 fA = *(const ulonglong2*)wfp;
                        ulonglong2 fB = *(const ulonglong2*)(wfp + 4);
                        ulonglong2 gA = *(const ulonglong2*)wgp;
                        ulonglong2 gB = *(const ulonglong2*)(wgp + 4);
                        u64 wf_[4] = {fA.x, fA.y, fB.x, fB.y};
                        u64 wg_[4] = {gA.x, gA.y, gB.x, gB.y};
                        #pragma unroll
                        for (int cc = 0; cc < 4; ++cc) {
                            pf[cc][0] = fma2(hv.x, wf_[cc], pf[cc][0]);
                            pf[cc][1] = fma2(hv.y, wf_[cc], pf[cc][1]);
                            pg[cc][0] = fma2(hv.x, wg_[cc], pg[cc][0]);
                            pg[cc][1] = fma2(hv.y, wg_[cc], pg[cc][1]);
                        }
                    }
                }
            }
            // y-pass
            #pragma unroll 2
            for (int k = 0; k < 32; ++k) {
                ulonglong2 yv = *(const ulonglong2*)(ybuf + k * TTH + lt0);
                const float* wfp = wd + F2T + (k * 32 + c0) * 2;
                const float* wgp = wd + G2T + (k * 32 + c0) * 2;
                ulonglong2 fA = *(const ulonglong2*)wfp;
                ulonglong2 fB = *(const ulonglong2*)(wfp + 4);
                ulonglong2 gA = *(const ulonglong2*)wgp;
                ulonglong2 gB = *(const ulonglong2*)(wgp + 4);
                u64 wf_[4] = {fA.x, fA.y, fB.x, fB.y};
                u64 wg_[4] = {gA.x, gA.y, gB.x, gB.y};
                #pragma unroll
                for (int cc = 0; cc < 4; ++cc) {
                    pf[cc][0] = fma2(yv.x, wf_[cc], pf[cc][0]);
                    pf[cc][1] = fma2(yv.y, wf_[cc], pf[cc][1]);
                    pg[cc][0] = fma2(yv.x, wg_[cc], pg[cc][0]);
                    pg[cc][1] = fma2(yv.y, wg_[cc], pg[cc][1]);
                }
            }
            #pragma unroll
            for (int cc = 0; cc < 4; ++cc)
                #pragma unroll
                for (int p = 0; p < 2; ++p) {
                    float f0, f1, g0, g1;
                    upk(pf[cc][p], f0, f1); upk(pg[cc][p], g0, g1);
                    zp[cc][p] = pk(fast_tanh(f0) * fast_sigmoid(g0),
                                   fast_tanh(f1) * fast_sigmoid(g1));
                }
        }
        __syncthreads();   // all reads of y done
        #pragma unroll
        for (int cc = 0; cc < 4; ++cc)
            *(ulonglong2*)(ybuf + (c0 + cc) * TTH + lt0) =
                make_ulonglong2(zp[cc][0], zp[cc][1]);
        __syncthreads();   // z complete

        // ---- G3: res += Ow @ z ----
        {
            u64 acc[4][2];
            #pragma unroll
            for (int a = 0; a < 4; ++a) { acc[a][0] = 0ULL; acc[a][1] = 0ULL; }

            #pragma unroll 2
            for (int k = 0; k < 32; ++k) {
                ulonglong2 zv = *(const ulonglong2*)(ybuf + k * TTH + lt0);
                const float* wp = wd + O2T + (k * 32 + c0) * 2;
                ulonglong2 wA = *(const ulonglong2*)wp;
                ulonglong2 wB = *(const ulonglong2*)(wp + 4);
                u64 w_[4] = {wA.x, wA.y, wB.x, wB.y};
                #pragma unroll
                for (int cc = 0; cc < 4; ++cc) {
                    acc[cc][0] = fma2(zv.x, w_[cc], acc[cc][0]);
                    acc[cc][1] = fma2(zv.y, w_[cc], acc[cc][1]);
                }
            }
            if (tg0 >= 0) {
                #pragma unroll
                for (int cc = 0; cc < 4; ++cc) {
                    float* rp = res + (c0 + cc) * TTH + lt0;
                    ulonglong2 rv = *(const ulonglong2*)rp;
                    *(ulonglong2*)rp = make_ulonglong2(add2(rv.x, acc[cc][0]),
                                                       add2(rv.y, acc[cc][1]));
                }
            }
        }
        __syncthreads();
    }

    // ---- relu(skip) -> ybuf; stage end1 transposed dup into wd ----
    for (int idx = tid; idx < 32 * TTH; idx += NTHREADS) {
        int ch = idx >> 9, lt = idx & (TTH - 1);
        int tg = tgb + lt;
        float xv = (tg >= 0 && tg < NT) ? x[b * NT + tg] : 0.f;
        ybuf[idx] = fmaxf(res[idx] - sw[ch] * xv, 0.f);
    }
    for (int j = tid; j < 8192; j += NTHREADS) {   // end1 [256][32] -> [k][s] dup
        int s = j >> 5, k = j & 31;
        float v = end1_w[j];
        *(float2*)(wd + (k * 256 + s) * 2) = make_float2(v, v);
    }
    __syncthreads();

    // ---- end head: chunks of 64 timesteps; ebuf[256][64] reuses res ----
    // thread = 4 skip-ch x 4 t : s0 = (tid>>4)*4 (64 blocks), t4 = (tid&15)*4
    float* ebuf = res;
    const int s0 = (tid >> 4) * 4;
    const int t4 = (tid & 15) * 4;
    for (int chunk = 0; chunk < 8; ++chunk) {
        const int ltc = HALO + chunk * 64 + t4;
        const bool active = (ltc < TTH);        // chunk 7 is partial (472 owned)
        u64 acc[4][2];
        #pragma unroll
        for (int a = 0; a < 4; ++a) { acc[a][0] = 0ULL; acc[a][1] = 0ULL; }

        if (active) {  // E1: e = relu(end1 @ skip)
            #pragma unroll 2
            for (int k = 0; k < 32; ++k) {
                ulonglong2 yv = *(const ulonglong2*)(ybuf + k * TTH + ltc);
                const float* wp = wd + (k * 256 + s0) * 2;
                ulonglong2 wA = *(const ulonglong2*)wp;
                ulonglong2 wB = *(const ulonglong2*)(wp + 4);
                u64 w_[4] = {wA.x, wA.y, wB.x, wB.y};
                #pragma unroll
                for (int ss = 0; ss < 4; ++ss) {
                    acc[ss][0] = fma2(yv.x, w_[ss], acc[ss][0]);
                    acc[ss][1] = fma2(yv.y, w_[ss], acc[ss][1]);
                }
            }
        }
        __syncthreads();   // prior chunk's E2 reads of ebuf complete
        if (active) {
            #pragma unroll
            for (int ss = 0; ss < 4; ++ss) {
                float* eo = ebuf + (s0 + ss) * 64 + t4;
                #pragma unroll
                for (int p = 0; p < 2; ++p) {
                    float a0, a1; upk(acc[ss][p], a0, a1);
                    *(float2*)(eo + 2 * p) = make_float2(fmaxf(a0, 0.f), fmaxf(a1, 0.f));
                }
            }
        }
        __syncthreads();   // e complete
        if (active) {  // E2: logit = end2 @ e
            u64 acc2[4][2];
            #pragma unroll
            for (int a = 0; a < 4; ++a) { acc2[a][0] = 0ULL; acc2[a][1] = 0ULL; }
            #pragma unroll 4
            for (int k = 0; k < 256; ++k) {
                ulonglong2 ev = *(const ulonglong2*)(ebuf + k * 64 + t4);
                #pragma unroll
                for (int cc = 0; cc < 4; ++cc) {
                    float w = __ldg(end2_w + (s0 + cc) * 256 + k);
                    u64 wp2 = pk(w, w);
                    acc2[cc][0] = fma2(ev.x, wp2, acc2[cc][0]);
                    acc2[cc][1] = fma2(ev.y, wp2, acc2[cc][1]);
                }
            }
            int tgc = tgb + ltc;
            #pragma unroll
            for (int cc = 0; cc < 4; ++cc) {
                float* op = out + ((size_t)(b * 256 + s0 + cc)) * NT + tgc;
                if (tgc + 4 <= NT) {
                    *(u64*)op       = acc2[cc][0];
                    *(u64*)(op + 2) = acc2[cc][1];
                } else {
                    #pragma unroll
                    for (int p = 0; p < 2; ++p) {
                        float a0, a1; upk(acc2[cc][p], a0, a1);
                        if (tgc + 2 * p     < NT) op[2 * p]     = a0;
                        if (tgc + 2 * p + 1 < NT) op[2 * p + 1] = a1;
                    }
                }
            }
        }
        __syncthreads();   // all E2 reads of ebuf done before next chunk overwrites
    }
}

extern "C" void kernel_launch(void* const* d_in, const int* in_sizes, int n_in,
                              void* d_out, int out_size) {
    const float* x       = (const float*)d_in[0];
    const float* h       = (const float*)d_in[1];
    const float* start_w = (const float*)d_in[2];
    const float* dil_w   = (const float*)d_in[3];
    const float* f_w     = (const float*)d_in[4];
    const float* g_w     = (const float*)d_in[5];
    const float* cf_w    = (const float*)d_in[6];
    const float* cg_w    = (const float*)d_in[7];
    const float* out_w   = (const float*)d_in[8];
    const float* end1_w  = (const float*)d_in[9];
    const float* end2_w  = (const float*)d_in[10];
    float* out = (float*)d_out;

    cudaFuncSetAttribute(wavenet_kernel,
                         cudaFuncAttributeMaxDynamicSharedMemorySize, SMEM_BYTES);
    wavenet_kernel<<<NB * TILES_PER_B, NTHREADS, SMEM_BYTES>>>(
        x, h, start_w, dil_w, f_w, g_w, cf_w, cg_w, out_w, end1_w, end2_w, out);
}

// round 11
// speedup vs baseline: 2.0090x; 1.3642x over previous
#include <cuda_runtime.h>

#define NB 4
#define NT 16384
#define NCOND 80
#define NLAY 40
#define TT 472
#define HALO 40
#define TTH 512
#define TILES_PER_B 35
#define NTHREADS 1024

// transposed NON-duplicated weights [k][c] (floats within wd)
#define D0T 0
#define D1T 1024
#define F2T 2048
#define G2T 3072
#define CF2T 4096
#define CG2T 6656
#define O2T 9216
#define WTOT 10240

#define SMEM_FLOATS (64*TTH + WTOT + 32)
#define SMEM_BYTES  (SMEM_FLOATS * 4)

typedef unsigned long long u64;

__device__ __forceinline__ u64 pk(float lo, float hi) {
    u64 r; asm("mov.b64 %0,{%1,%2};" : "=l"(r) : "f"(lo), "f"(hi)); return r;
}
__device__ __forceinline__ void upk(u64 v, float& a, float& b) {
    asm("mov.b64 {%0,%1},%2;" : "=f"(a), "=f"(b) : "l"(v));
}
__device__ __forceinline__ u64 fma2(u64 a, u64 b, u64 c) {
    u64 d; asm("fma.rn.f32x2 %0,%1,%2,%3;" : "=l"(d) : "l"(a), "l"(b), "l"(c)); return d;
}
__device__ __forceinline__ float fast_sigmoid(float v) {
    v = fminf(fmaxf(v, -30.f), 30.f);
    return __fdividef(1.f, 1.f + __expf(-v));
}
__device__ __forceinline__ float fast_tanh(float v) {
    v = fminf(fmaxf(v, -15.f), 15.f);
    float e2 = __expf(2.f * v);
    return __fdividef(e2 - 1.f, e2 + 1.f);
}

__global__ void __launch_bounds__(NTHREADS, 1)
wavenet_kernel(const float* __restrict__ x, const float* __restrict__ h,
               const float* __restrict__ start_w, const float* __restrict__ dil_w,
               const float* __restrict__ f_w, const float* __restrict__ g_w,
               const float* __restrict__ cf_w, const float* __restrict__ cg_w,
               const float* __restrict__ out_w, const float* __restrict__ end1_w,
               const float* __restrict__ end2_w, float* __restrict__ out)
{
    extern __shared__ float smem[];
    float* res  = smem;               // [32][TTH]
    float* ybuf = smem + 32 * TTH;    // [32][TTH]
    float* wd   = smem + 64 * TTH;    // [WTOT] transposed weights
    float* sw   = wd + WTOT;          // [32]

    const int tid = threadIdx.x;
    const int b   = blockIdx.x / TILES_PER_B;
    const int tc  = blockIdx.x % TILES_PER_B;
    const int tgb = tc * TT - HALO;

    if (tid < 32) sw[tid] = start_w[tid];
    for (int idx = tid; idx < 32 * TTH; idx += NTHREADS) {
        int ch = idx >> 9, lt = idx & (TTH - 1);
        int tg = tgb + lt;
        float xv = (tg >= 0 && tg < NT) ? x[b * NT + tg] : 0.f;
        res[idx] = start_w[ch] * xv;
    }
    __syncthreads();

    // thread tile: 4 ch (2 f32x2 channel-pairs) x 4 t, lanes contiguous in time
    const int c0  = (tid >> 7) * 4;        // 0,4,...,28
    const int lt0 = (tid & 127) * 4;       // 0..508
    const int tg0 = tgb + lt0;
    const bool hval = (tg0 >= 0 && tg0 + 4 <= NT);
    const float* hb = h + ((size_t)(b * NCOND)) * NT + tg0;

    for (int l = 0; l < NLAY; ++l) {
        // ---- stage weights transposed [k][c]; dest-major => conflict-free STS ----
        {
            const float* dl  = dil_w + l * 2048;
            const float* fl  = f_w   + l * 1024;
            const float* gl  = g_w   + l * 1024;
            const float* cfl = cf_w  + l * 2560;
            const float* cgl = cg_w  + l * 2560;
            const float* ol  = out_w + l * 1024;
            for (int j = tid; j < 1024; j += NTHREADS) {     // dil
                int i = j >> 5, c = j & 31;
                float2 w = *(const float2*)(dl + (c * 32 + i) * 2);
                wd[D0T + j] = w.x;
                wd[D1T + j] = w.y;
            }
            for (int j = tid; j < 512; j += NTHREADS) {      // f, g (k in pairs)
                int k2 = j >> 5, c = j & 31;
                float2 vf = *(const float2*)(fl + c * 32 + 2 * k2);
                float2 vg = *(const float2*)(gl + c * 32 + 2 * k2);
                wd[F2T + (2 * k2) * 32 + c]     = vf.x;
                wd[F2T + (2 * k2 + 1) * 32 + c] = vf.y;
                wd[G2T + (2 * k2) * 32 + c]     = vg.x;
                wd[G2T + (2 * k2 + 1) * 32 + c] = vg.y;
            }
            for (int j = tid; j < 1280; j += NTHREADS) {     // cf, cg
                int k2 = j >> 5, c = j & 31;
                float2 vf = *(const float2*)(cfl + c * 80 + 2 * k2);
                float2 vg = *(const float2*)(cgl + c * 80 + 2 * k2);
                wd[CF2T + (2 * k2) * 32 + c]     = vf.x;
                wd[CF2T + (2 * k2 + 1) * 32 + c] = vf.y;
                wd[CG2T + (2 * k2) * 32 + c]     = vg.x;
                wd[CG2T + (2 * k2 + 1) * 32 + c] = vg.y;
            }
            for (int j = tid; j < 512; j += NTHREADS) {      // out
                int k2 = j >> 5, c = j & 31;
                float2 v = *(const float2*)(ol + c * 32 + 2 * k2);
                wd[O2T + (2 * k2) * 32 + c]     = v.x;
                wd[O2T + (2 * k2 + 1) * 32 + c] = v.y;
            }
        }
        __syncthreads();

        // ---- G1: y[c,t] = W0[c,i]*res[i,t-1] + W1[c,i]*res[i,t] ----
        {
            u64 a0[4], a1[4];
            #pragma unroll
            for (int t = 0; t < 4; ++t) { a0[t] = 0ULL; a1[t] = 0ULL; }

            #pragma unroll 2
            for (int i = 0; i < 32; ++i) {
                const float* rr = res + i * TTH + lt0;
                float4 rv = *(const float4*)rr;
                float rm1 = (lt0 > 0) ? rr[-1] : 0.f;
                u64 pm = pk(rm1, rm1), p0 = pk(rv.x, rv.x), p1 = pk(rv.y, rv.y),
                    p2 = pk(rv.z, rv.z), p3 = pk(rv.w, rv.w);
                ulonglong2 w0 = *(const ulonglong2*)(wd + D0T + i * 32 + c0);
                ulonglong2 w1 = *(const ulonglong2*)(wd + D1T + i * 32 + c0);
                a0[0] = fma2(pm, w0.x, a0[0]); a0[0] = fma2(p0, w1.x, a0[0]);
                a0[1] = fma2(p0, w0.x, a0[1]); a0[1] = fma2(p1, w1.x, a0[1]);
                a0[2] = fma2(p1, w0.x, a0[2]); a0[2] = fma2(p2, w1.x, a0[2]);
                a0[3] = fma2(p2, w0.x, a0[3]); a0[3] = fma2(p3, w1.x, a0[3]);
                a1[0] = fma2(pm, w0.y, a1[0]); a1[0] = fma2(p0, w1.y, a1[0]);
                a1[1] = fma2(p0, w0.y, a1[1]); a1[1] = fma2(p1, w1.y, a1[1]);
                a1[2] = fma2(p1, w0.y, a1[2]); a1[2] = fma2(p2, w1.y, a1[2]);
                a1[3] = fma2(p2, w0.y, a1[3]); a1[3] = fma2(p3, w1.y, a1[3]);
            }
            float v0[4], v1[4], v2[4], v3[4];
            #pragma unroll
            for (int t = 0; t < 4; ++t) {
                upk(a0[t], v0[t], v1[t]);
                upk(a1[t], v2[t], v3[t]);
            }
            *(float4*)(ybuf + (c0 + 0) * TTH + lt0) = make_float4(v0[0], v0[1], v0[2], v0[3]);
            *(float4*)(ybuf + (c0 + 1) * TTH + lt0) = make_float4(v1[0], v1[1], v1[2], v1[3]);
            *(float4*)(ybuf + (c0 + 2) * TTH + lt0) = make_float4(v2[0], v2[1], v2[2], v2[3]);
            *(float4*)(ybuf + (c0 + 3) * TTH + lt0) = make_float4(v3[0], v3[1], v3[2], v3[3]);
        }
        __syncthreads();

        // ---- G2: z = tanh(F@y + CF@h) * sigmoid(G@y + CG@h) ----
        float z0[4], z1[4], z2[4], z3[4];
        {
            u64 pf0[4], pf1[4], pg0[4], pg1[4];
            #pragma unroll
            for (int t = 0; t < 4; ++t) {
                pf0[t] = 0ULL; pf1[t] = 0ULL; pg0[t] = 0ULL; pg1[t] = 0ULL;
            }

            if (hval) {  // conditioning pass (batched LDG, MLP 2)
                #pragma unroll 1
                for (int k = 0; k < NCOND; k += 2) {
                    float4 hA = *(const float4*)(hb + (size_t)k * NT);
                    float4 hB = *(const float4*)(hb + (size_t)(k + 1) * NT);
                    #pragma unroll
                    for (int q = 0; q < 2; ++q) {
                        float4 hv = q ? hB : hA;
                        u64 p0 = pk(hv.x, hv.x), p1 = pk(hv.y, hv.y),
                            p2 = pk(hv.z, hv.z), p3 = pk(hv.w, hv.w);
                        ulonglong2 wf = *(const ulonglong2*)(wd + CF2T + (k + q) * 32 + c0);
                        pf0[0] = fma2(p0, wf.x, pf0[0]); pf0[1] = fma2(p1, wf.x, pf0[1]);
                        pf0[2] = fma2(p2, wf.x, pf0[2]); pf0[3] = fma2(p3, wf.x, pf0[3]);
                        pf1[0] = fma2(p0, wf.y, pf1[0]); pf1[1] = fma2(p1, wf.y, pf1[1]);
                        pf1[2] = fma2(p2, wf.y, pf1[2]); pf1[3] = fma2(p3, wf.y, pf1[3]);
                        ulonglong2 wg = *(const ulonglong2*)(wd + CG2T + (k + q) * 32 + c0);
                        pg0[0] = fma2(p0, wg.x, pg0[0]); pg0[1] = fma2(p1, wg.x, pg0[1]);
                        pg0[2] = fma2(p2, wg.x, pg0[2]); pg0[3] = fma2(p3, wg.x, pg0[3]);
                        pg1[0] = fma2(p0, wg.y, pg1[0]); pg1[1] = fma2(p1, wg.y, pg1[1]);
                        pg1[2] = fma2(p2, wg.y, pg1[2]); pg1[3] = fma2(p3, wg.y, pg1[3]);
                    }
                }
            }
            // y pass
            #pragma unroll 2
            for (int k = 0; k < 32; ++k) {
                float4 yv = *(const float4*)(ybuf + k * TTH + lt0);
                u64 p0 = pk(yv.x, yv.x), p1 = pk(yv.y, yv.y),
                    p2 = pk(yv.z, yv.z), p3 = pk(yv.w, yv.w);
                ulonglong2 wf = *(const ulonglong2*)(wd + F2T + k * 32 + c0);
                pf0[0] = fma2(p0, wf.x, pf0[0]); pf0[1] = fma2(p1, wf.x, pf0[1]);
                pf0[2] = fma2(p2, wf.x, pf0[2]); pf0[3] = fma2(p3, wf.x, pf0[3]);
                pf1[0] = fma2(p0, wf.y, pf1[0]); pf1[1] = fma2(p1, wf.y, pf1[1]);
                pf1[2] = fma2(p2, wf.y, pf1[2]); pf1[3] = fma2(p3, wf.y, pf1[3]);
                ulonglong2 wg = *(const ulonglong2*)(wd + G2T + k * 32 + c0);
                pg0[0] = fma2(p0, wg.x, pg0[0]); pg0[1] = fma2(p1, wg.x, pg0[1]);
                pg0[2] = fma2(p2, wg.x, pg0[2]); pg0[3] = fma2(p3, wg.x, pg0[3]);
                pg1[0] = fma2(p0, wg.y, pg1[0]); pg1[1] = fma2(p1, wg.y, pg1[1]);
                pg1[2] = fma2(p2, wg.y, pg1[2]); pg1[3] = fma2(p3, wg.y, pg1[3]);
            }
            #pragma unroll
            for (int t = 0; t < 4; ++t) {
                float fl_, fh_, gl_, gh_;
                upk(pf0[t], fl_, fh_); upk(pg0[t], gl_, gh_);
                z0[t] = fast_tanh(fl_) * fast_sigmoid(gl_);
                z1[t] = fast_tanh(fh_) * fast_sigmoid(gh_);
                upk(pf1[t], fl_, fh_); upk(pg1[t], gl_, gh_);
                z2[t] = fast_tanh(fl_) * fast_sigmoid(gl_);
                z3[t] = fast_tanh(fh_) * fast_sigmoid(gh_);
            }
        }
        __syncthreads();   // all reads of y done
        *(float4*)(ybuf + (c0 + 0) * TTH + lt0) = make_float4(z0[0], z0[1], z0[2], z0[3]);
        *(float4*)(ybuf + (c0 + 1) * TTH + lt0) = make_float4(z1[0], z1[1], z1[2], z1[3]);
        *(float4*)(ybuf + (c0 + 2) * TTH + lt0) = make_float4(z2[0], z2[1], z2[2], z2[3]);
        *(float4*)(ybuf + (c0 + 3) * TTH + lt0) = make_float4(z3[0], z3[1], z3[2], z3[3]);
        __syncthreads();   // z complete

        // ---- G3: res += Ow @ z ----
        {
            u64 a0[4], a1[4];
            #pragma unroll
            for (int t = 0; t < 4; ++t) { a0[t] = 0ULL; a1[t] = 0ULL; }

            #pragma unroll 2
            for (int k = 0; k < 32; ++k) {
                float4 zv = *(const float4*)(ybuf + k * TTH + lt0);
                u64 p0 = pk(zv.x, zv.x), p1 = pk(zv.y, zv.y),
                    p2 = pk(zv.z, zv.z), p3 = pk(zv.w, zv.w);
                ulonglong2 w = *(const ulonglong2*)(wd + O2T + k * 32 + c0);
                a0[0] = fma2(p0, w.x, a0[0]); a0[1] = fma2(p1, w.x, a0[1]);
                a0[2] = fma2(p2, w.x, a0[2]); a0[3] = fma2(p3, w.x, a0[3]);
                a1[0] = fma2(p0, w.y, a1[0]); a1[1] = fma2(p1, w.y, a1[1]);
                a1[2] = fma2(p2, w.y, a1[2]); a1[3] = fma2(p3, w.y, a1[3]);
            }
            if (tg0 >= 0) {
                float v0[4], v1[4], v2[4], v3[4];
                #pragma unroll
                for (int t = 0; t < 4; ++t) {
                    upk(a0[t], v0[t], v1[t]);
                    upk(a1[t], v2[t], v3[t]);
                }
                float* r0 = res + (c0 + 0) * TTH + lt0;
                float* r1 = res + (c0 + 1) * TTH + lt0;
                float* r2 = res + (c0 + 2) * TTH + lt0;
                float* r3 = res + (c0 + 3) * TTH + lt0;
                float4 q0 = *(float4*)r0, q1 = *(float4*)r1,
                       q2 = *(float4*)r2, q3 = *(float4*)r3;
                *(float4*)r0 = make_float4(q0.x + v0[0], q0.y + v0[1], q0.z + v0[2], q0.w + v0[3]);
                *(float4*)r1 = make_float4(q1.x + v1[0], q1.y + v1[1], q1.z + v1[2], q1.w + v1[3]);
                *(float4*)r2 = make_float4(q2.x + v2[0], q2.y + v2[1], q2.z + v2[2], q2.w + v2[3]);
                *(float4*)r3 = make_float4(q3.x + v3[0], q3.y + v3[1], q3.z + v3[2], q3.w + v3[3]);
            }
        }
        __syncthreads();
    }

    // ---- relu(skip) -> ybuf; stage end1 transposed [k][s] into wd ----
    for (int idx = tid; idx < 32 * TTH; idx += NTHREADS) {
        int ch = idx >> 9, lt = idx & (TTH - 1);
        int tg = tgb + lt;
        float xv = (tg >= 0 && tg < NT) ? x[b * NT + tg] : 0.f;
        ybuf[idx] = fmaxf(res[idx] - sw[ch] * xv, 0.f);
    }
    for (int j = tid; j < 8192; j += NTHREADS) {   // dest [k][s]: conflict-free STS
        int k = j >> 8, s = j & 255;
        wd[j] = end1_w[s * 32 + k];
    }
    __syncthreads();

    // ---- end head: chunks of 64 timesteps; ebuf[256][64] reuses res ----
    float* ebuf = res;
    const int s0 = (tid >> 4) * 4;   // 0..252 step 4
    const int t4 = (tid & 15) * 4;   // 0..60
    for (int chunk = 0; chunk < 8; ++chunk) {
        const int ltc = HALO + chunk * 64 + t4;
        const bool active = (ltc < TTH);    // chunk 7 partial
        u64 a0[4], a1[4];
        #pragma unroll
        for (int t = 0; t < 4; ++t) { a0[t] = 0ULL; a1[t] = 0ULL; }

        if (active) {  // E1: e = relu(end1 @ skip), channel-pair lanes
            #pragma unroll 2
            for (int k = 0; k < 32; ++k) {
                float4 yv = *(const float4*)(ybuf + k * TTH + ltc);
                u64 p0 = pk(yv.x, yv.x), p1 = pk(yv.y, yv.y),
                    p2 = pk(yv.z, yv.z), p3 = pk(yv.w, yv.w);
                ulonglong2 w = *(const ulonglong2*)(wd + k * 256 + s0);
                a0[0] = fma2(p0, w.x, a0[0]); a0[1] = fma2(p1, w.x, a0[1]);
                a0[2] = fma2(p2, w.x, a0[2]); a0[3] = fma2(p3, w.x, a0[3]);
                a1[0] = fma2(p0, w.y, a1[0]); a1[1] = fma2(p1, w.y, a1[1]);
                a1[2] = fma2(p2, w.y, a1[2]); a1[3] = fma2(p3, w.y, a1[3]);
            }
        }
        __syncthreads();   // prior chunk's E2 reads of ebuf complete
        if (active) {
            float v0[4], v1[4], v2[4], v3[4];
            #pragma unroll
            for (int t = 0; t < 4; ++t) {
                upk(a0[t], v0[t], v1[t]);
                upk(a1[t], v2[t], v3[t]);
            }
            *(float4*)(ebuf + (s0 + 0) * 64 + t4) =
                make_float4(fmaxf(v0[0],0.f), fmaxf(v0[1],0.f), fmaxf(v0[2],0.f), fmaxf(v0[3],0.f));
            *(float4*)(ebuf + (s0 + 1) * 64 + t4) =
                make_float4(fmaxf(v1[0],0.f), fmaxf(v1[1],0.f), fmaxf(v1[2],0.f), fmaxf(v1[3],0.f));
            *(float4*)(ebuf + (s0 + 2) * 64 + t4) =
                make_float4(fmaxf(v2[0],0.f), fmaxf(v2[1],0.f), fmaxf(v2[2],0.f), fmaxf(v2[3],0.f));
            *(float4*)(ebuf + (s0 + 3) * 64 + t4) =
                make_float4(fmaxf(v3[0],0.f), fmaxf(v3[1],0.f), fmaxf(v3[2],0.f), fmaxf(v3[3],0.f));
        }
        __syncthreads();   // e complete
        if (active) {  // E2: logit = end2 @ e (time-pair lanes, gmem weights)
            u64 acc2[4][2];
            #pragma unroll
            for (int a = 0; a < 4; ++a) { acc2[a][0] = 0ULL; acc2[a][1] = 0ULL; }
            #pragma unroll 4
            for (int k = 0; k < 256; ++k) {
                ulonglong2 ev = *(const ulonglong2*)(ebuf + k * 64 + t4);
                #pragma unroll
                for (int cc = 0; cc < 4; ++cc) {
                    float w = __ldg(end2_w + (s0 + cc) * 256 + k);
                    u64 wp2 = pk(w, w);
                    acc2[cc][0] = fma2(ev.x, wp2, acc2[cc][0]);
                    acc2[cc][1] = fma2(ev.y, wp2, acc2[cc][1]);
                }
            }
            int tgc = tgb + ltc;
            #pragma unroll
            for (int cc = 0; cc < 4; ++cc) {
                float* op = out + ((size_t)(b * 256 + s0 + cc)) * NT + tgc;
                if (tgc + 4 <= NT) {
                    *(u64*)op       = acc2[cc][0];
                    *(u64*)(op + 2) = acc2[cc][1];
                } else {
                    #pragma unroll
                    for (int p = 0; p < 2; ++p) {
                        float a0_, a1_; upk(acc2[cc][p], a0_, a1_);
                        if (tgc + 2 * p     < NT) op[2 * p]     = a0_;
                        if (tgc + 2 * p + 1 < NT) op[2 * p + 1] = a1_;
                    }
                }
            }
        }
        __syncthreads();   // all E2 reads of ebuf done before next chunk overwrites
    }
}

extern "C" void kernel_launch(void* const* d_in, const int* in_sizes, int n_in,
                              void* d_out, int out_size) {
    const float* x       = (const float*)d_in[0];
    const float* h       = (const float*)d_in[1];
    const float* start_w = (const float*)d_in[2];
    const float* dil_w   = (const float*)d_in[3];
    const float* f_w     = (const float*)d_in[4];
    const float* g_w     = (const float*)d_in[5];
    const float* cf_w    = (const float*)d_in[6];
    const float* cg_w    = (const float*)d_in[7];
    const float* out_w   = (const float*)d_in[8];
    const float* end1_w  = (const float*)d_in[9];
    const float* end2_w  = (const float*)d_in[10];
    float* out = (float*)d_out;

    cudaFuncSetAttribute(wavenet_kernel,
                         cudaFuncAttributeMaxDynamicSharedMemorySize, SMEM_BYTES);
    wavenet_kernel<<<NB * TILES_PER_B, NTHREADS, SMEM_BYTES>>>(
        x, h, start_w, dil_w, f_w, g_w, cf_w, cg_w, out_w, end1_w, end2_w, out);
}

// round 13
// speedup vs baseline: 2.1346x; 1.0625x over previous
#include <cuda_runtime.h>

#define NB 4
#define NT 16384
#define NCOND 80
#define NLAY 40
#define TT 472
#define HALO 40
#define TTH 512
#define TILES_PER_B 35
#define NTHREADS 1024

// per-layer transposed weights [k][c] (floats), two staging slots
#define D0T 0
#define D1T 1024
#define F2T 2048
#define G2T 3072
#define CF2T 4096
#define CG2T 6656
#define O2T 9216
#define WLAY 10240
#define WTOT (2*WLAY)

#define SMEM_FLOATS (64*TTH + WTOT + 32)
#define SMEM_BYTES  (SMEM_FLOATS * 4)

typedef unsigned long long u64;

__device__ __forceinline__ u64 pk(float lo, float hi) {
    u64 r; asm("mov.b64 %0,{%1,%2};" : "=l"(r) : "f"(lo), "f"(hi)); return r;
}
__device__ __forceinline__ void upk(u64 v, float& a, float& b) {
    asm("mov.b64 {%0,%1},%2;" : "=f"(a), "=f"(b) : "l"(v));
}
__device__ __forceinline__ u64 fma2(u64 a, u64 b, u64 c) {
    u64 d; asm("fma.rn.f32x2 %0,%1,%2,%3;" : "=l"(d) : "l"(a), "l"(b), "l"(c)); return d;
}
__device__ __forceinline__ float fast_sigmoid(float v) {
    v = fminf(fmaxf(v, -30.f), 30.f);
    return __fdividef(1.f, 1.f + __expf(-v));
}
__device__ __forceinline__ float fast_tanh(float v) {
    v = fminf(fmaxf(v, -15.f), 15.f);
    float e2 = __expf(2.f * v);
    return __fdividef(e2 - 1.f, e2 + 1.f);
}

__global__ void __launch_bounds__(NTHREADS, 1)
wavenet_kernel(const float* __restrict__ x, const float* __restrict__ h,
               const float* __restrict__ start_w, const float* __restrict__ dil_w,
               const float* __restrict__ f_w, const float* __restrict__ g_w,
               const float* __restrict__ cf_w, const float* __restrict__ cg_w,
               const float* __restrict__ out_w, const float* __restrict__ end1_w,
               const float* __restrict__ end2_w, float* __restrict__ out)
{
    extern __shared__ float smem[];
    float* res  = smem;               // [32][TTH]
    float* ybuf = smem + 32 * TTH;    // [32][TTH]
    float* wd   = smem + 64 * TTH;    // [2][WLAY]
    float* sw   = wd + WTOT;          // [32]

    const int tid = threadIdx.x;
    const int b   = blockIdx.x / TILES_PER_B;
    const int tc  = blockIdx.x % TILES_PER_B;
    const int tgb = tc * TT - HALO;

    if (tid < 32) sw[tid] = start_w[tid];
    for (int idx = tid; idx < 32 * TTH; idx += NTHREADS) {
        int ch = idx >> 9, lt = idx & (TTH - 1);
        int tg = tgb + lt;
        float xv = (tg >= 0 && tg < NT) ? x[b * NT + tg] : 0.f;
        res[idx] = start_w[ch] * xv;
    }
    __syncthreads();

    // thread tile: 4 ch (2 f32x2 channel-pairs) x 4 t, lanes contiguous in time
    const int c0  = (tid >> 7) * 4;        // 0,4,...,28
    const int lt0 = (tid & 127) * 4;       // 0..508
    const int tg0 = tgb + lt0;
    const bool hval = (tg0 >= 0 && tg0 + 4 <= NT);
    const float* hb = h + ((size_t)(b * NCOND)) * NT + tg0;

    for (int l = 0; l < NLAY; l += 2) {
        // ---- stage TWO layers' weights transposed [k][c]; conflict-free STS ----
        #pragma unroll
        for (int s = 0; s < 2; ++s) {
            float* w = wd + s * WLAY;
            const float* dl  = dil_w + (l + s) * 2048;
            const float* fl  = f_w   + (l + s) * 1024;
            const float* gl  = g_w   + (l + s) * 1024;
            const float* cfl = cf_w  + (l + s) * 2560;
            const float* cgl = cg_w  + (l + s) * 2560;
            const float* ol  = out_w + (l + s) * 1024;
            for (int j = tid; j < 1024; j += NTHREADS) {     // dil
                int i = j >> 5, c = j & 31;
                float2 wv = *(const float2*)(dl + (c * 32 + i) * 2);
                w[D0T + j] = wv.x;
                w[D1T + j] = wv.y;
            }
            for (int j = tid; j < 512; j += NTHREADS) {      // f, g
                int k2 = j >> 5, c = j & 31;
                float2 vf = *(const float2*)(fl + c * 32 + 2 * k2);
                float2 vg = *(const float2*)(gl + c * 32 + 2 * k2);
                w[F2T + (2 * k2) * 32 + c]     = vf.x;
                w[F2T + (2 * k2 + 1) * 32 + c] = vf.y;
                w[G2T + (2 * k2) * 32 + c]     = vg.x;
                w[G2T + (2 * k2 + 1) * 32 + c] = vg.y;
            }
            for (int j = tid; j < 1280; j += NTHREADS) {     // cf, cg
                int k2 = j >> 5, c = j & 31;
                float2 vf = *(const float2*)(cfl + c * 80 + 2 * k2);
                float2 vg = *(const float2*)(cgl + c * 80 + 2 * k2);
                w[CF2T + (2 * k2) * 32 + c]     = vf.x;
                w[CF2T + (2 * k2 + 1) * 32 + c] = vf.y;
                w[CG2T + (2 * k2) * 32 + c]     = vg.x;
                w[CG2T + (2 * k2 + 1) * 32 + c] = vg.y;
            }
            for (int j = tid; j < 512; j += NTHREADS) {      // out
                int k2 = j >> 5, c = j & 31;
                float2 v = *(const float2*)(ol + c * 32 + 2 * k2);
                w[O2T + (2 * k2) * 32 + c]     = v.x;
                w[O2T + (2 * k2 + 1) * 32 + c] = v.y;
            }
        }
        __syncthreads();

        #pragma unroll 1
        for (int s = 0; s < 2; ++s) {
            const float* wdl = wd + s * WLAY;

            // ---- G1: y[c,t] = W0[c,i]*res[i,t-1] + W1[c,i]*res[i,t] ----
            {
                u64 a0[4], a1[4];
                #pragma unroll
                for (int t = 0; t < 4; ++t) { a0[t] = 0ULL; a1[t] = 0ULL; }

                #pragma unroll 2
                for (int i = 0; i < 32; ++i) {
                    const float* rr = res + i * TTH + lt0;
                    float4 rv = *(const float4*)rr;
                    float rm1 = (lt0 > 0) ? rr[-1] : 0.f;
                    u64 pm = pk(rm1, rm1), p0 = pk(rv.x, rv.x), p1 = pk(rv.y, rv.y),
                        p2 = pk(rv.z, rv.z), p3 = pk(rv.w, rv.w);
                    ulonglong2 w0 = *(const ulonglong2*)(wdl + D0T + i * 32 + c0);
                    ulonglong2 w1 = *(const ulonglong2*)(wdl + D1T + i * 32 + c0);
                    a0[0] = fma2(pm, w0.x, a0[0]); a0[0] = fma2(p0, w1.x, a0[0]);
                    a0[1] = fma2(p0, w0.x, a0[1]); a0[1] = fma2(p1, w1.x, a0[1]);
                    a0[2] = fma2(p1, w0.x, a0[2]); a0[2] = fma2(p2, w1.x, a0[2]);
                    a0[3] = fma2(p2, w0.x, a0[3]); a0[3] = fma2(p3, w1.x, a0[3]);
                    a1[0] = fma2(pm, w0.y, a1[0]); a1[0] = fma2(p0, w1.y, a1[0]);
                    a1[1] = fma2(p0, w0.y, a1[1]); a1[1] = fma2(p1, w1.y, a1[1]);
                    a1[2] = fma2(p1, w0.y, a1[2]); a1[2] = fma2(p2, w1.y, a1[2]);
                    a1[3] = fma2(p2, w0.y, a1[3]); a1[3] = fma2(p3, w1.y, a1[3]);
                }
                float v0[4], v1[4], v2[4], v3[4];
                #pragma unroll
                for (int t = 0; t < 4; ++t) {
                    upk(a0[t], v0[t], v1[t]);
                    upk(a1[t], v2[t], v3[t]);
                }
                *(float4*)(ybuf + (c0 + 0) * TTH + lt0) = make_float4(v0[0], v0[1], v0[2], v0[3]);
                *(float4*)(ybuf + (c0 + 1) * TTH + lt0) = make_float4(v1[0], v1[1], v1[2], v1[3]);
                *(float4*)(ybuf + (c0 + 2) * TTH + lt0) = make_float4(v2[0], v2[1], v2[2], v2[3]);
                *(float4*)(ybuf + (c0 + 3) * TTH + lt0) = make_float4(v3[0], v3[1], v3[2], v3[3]);
            }
            __syncthreads();

            // ---- G2: z = tanh(F@y + CF@h) * sigmoid(G@y + CG@h) ----
            float z0[4], z1[4], z2[4], z3[4];
            {
                u64 pf0[4], pf1[4], pg0[4], pg1[4];
                #pragma unroll
                for (int t = 0; t < 4; ++t) {
                    pf0[t] = 0ULL; pf1[t] = 0ULL; pg0[t] = 0ULL; pg1[t] = 0ULL;
                }

                if (hval) {  // conditioning pass (batched LDG)
                    #pragma unroll 2
                    for (int k = 0; k < NCOND; k += 2) {
                        float4 hA = *(const float4*)(hb + (size_t)k * NT);
                        float4 hB = *(const float4*)(hb + (size_t)(k + 1) * NT);
                        #pragma unroll
                        for (int q = 0; q < 2; ++q) {
                            float4 hv = q ? hB : hA;
                            u64 p0 = pk(hv.x, hv.x), p1 = pk(hv.y, hv.y),
                                p2 = pk(hv.z, hv.z), p3 = pk(hv.w, hv.w);
                            ulonglong2 wf = *(const ulonglong2*)(wdl + CF2T + (k + q) * 32 + c0);
                            pf0[0] = fma2(p0, wf.x, pf0[0]); pf0[1] = fma2(p1, wf.x, pf0[1]);
                            pf0[2] = fma2(p2, wf.x, pf0[2]); pf0[3] = fma2(p3, wf.x, pf0[3]);
                            pf1[0] = fma2(p0, wf.y, pf1[0]); pf1[1] = fma2(p1, wf.y, pf1[1]);
                            pf1[2] = fma2(p2, wf.y, pf1[2]); pf1[3] = fma2(p3, wf.y, pf1[3]);
                            ulonglong2 wg = *(const ulonglong2*)(wdl + CG2T + (k + q) * 32 + c0);
                            pg0[0] = fma2(p0, wg.x, pg0[0]); pg0[1] = fma2(p1, wg.x, pg0[1]);
                            pg0[2] = fma2(p2, wg.x, pg0[2]); pg0[3] = fma2(p3, wg.x, pg0[3]);
                            pg1[0] = fma2(p0, wg.y, pg1[0]); pg1[1] = fma2(p1, wg.y, pg1[1]);
                            pg1[2] = fma2(p2, wg.y, pg1[2]); pg1[3] = fma2(p3, wg.y, pg1[3]);
                        }
                    }
                }
                // y pass
                #pragma unroll 4
                for (int k = 0; k < 32; ++k) {
                    float4 yv = *(const float4*)(ybuf + k * TTH + lt0);
                    u64 p0 = pk(yv.x, yv.x), p1 = pk(yv.y, yv.y),
                        p2 = pk(yv.z, yv.z), p3 = pk(yv.w, yv.w);
                    ulonglong2 wf = *(const ulonglong2*)(wdl + F2T + k * 32 + c0);
                    pf0[0] = fma2(p0, wf.x, pf0[0]); pf0[1] = fma2(p1, wf.x, pf0[1]);
                    pf0[2] = fma2(p2, wf.x, pf0[2]); pf0[3] = fma2(p3, wf.x, pf0[3]);
                    pf1[0] = fma2(p0, wf.y, pf1[0]); pf1[1] = fma2(p1, wf.y, pf1[1]);
                    pf1[2] = fma2(p2, wf.y, pf1[2]); pf1[3] = fma2(p3, wf.y, pf1[3]);
                    ulonglong2 wg = *(const ulonglong2*)(wdl + G2T + k * 32 + c0);
                    pg0[0] = fma2(p0, wg.x, pg0[0]); pg0[1] = fma2(p1, wg.x, pg0[1]);
                    pg0[2] = fma2(p2, wg.x, pg0[2]); pg0[3] = fma2(p3, wg.x, pg0[3]);
                    pg1[0] = fma2(p0, wg.y, pg1[0]); pg1[1] = fma2(p1, wg.y, pg1[1]);
                    pg1[2] = fma2(p2, wg.y, pg1[2]); pg1[3] = fma2(p3, wg.y, pg1[3]);
                }
                #pragma unroll
                for (int t = 0; t < 4; ++t) {
                    float fl_, fh_, gl_, gh_;
                    upk(pf0[t], fl_, fh_); upk(pg0[t], gl_, gh_);
                    z0[t] = fast_tanh(fl_) * fast_sigmoid(gl_);
                    z1[t] = fast_tanh(fh_) * fast_sigmoid(gh_);
                    upk(pf1[t], fl_, fh_); upk(pg1[t], gl_, gh_);
                    z2[t] = fast_tanh(fl_) * fast_sigmoid(gl_);
                    z3[t] = fast_tanh(fh_) * fast_sigmoid(gh_);
                }
            }
            __syncthreads();   // all reads of y done
            *(float4*)(ybuf + (c0 + 0) * TTH + lt0) = make_float4(z0[0], z0[1], z0[2], z0[3]);
            *(float4*)(ybuf + (c0 + 1) * TTH + lt0) = make_float4(z1[0], z1[1], z1[2], z1[3]);
            *(float4*)(ybuf + (c0 + 2) * TTH + lt0) = make_float4(z2[0], z2[1], z2[2], z2[3]);
            *(float4*)(ybuf + (c0 + 3) * TTH + lt0) = make_float4(z3[0], z3[1], z3[2], z3[3]);
            __syncthreads();   // z complete

            // ---- G3: res += Ow @ z ----
            {
                u64 a0[4], a1[4];
                #pragma unroll
                for (int t = 0; t < 4; ++t) { a0[t] = 0ULL; a1[t] = 0ULL; }

                #pragma unroll 4
                for (int k = 0; k < 32; ++k) {
                    float4 zv = *(const float4*)(ybuf + k * TTH + lt0);
                    u64 p0 = pk(zv.x, zv.x), p1 = pk(zv.y, zv.y),
                        p2 = pk(zv.z, zv.z), p3 = pk(zv.w, zv.w);
                    ulonglong2 w = *(const ulonglong2*)(wdl + O2T + k * 32 + c0);
                    a0[0] = fma2(p0, w.x, a0[0]); a0[1] = fma2(p1, w.x, a0[1]);
                    a0[2] = fma2(p2, w.x, a0[2]); a0[3] = fma2(p3, w.x, a0[3]);
                    a1[0] = fma2(p0, w.y, a1[0]); a1[1] = fma2(p1, w.y, a1[1]);
                    a1[2] = fma2(p2, w.y, a1[2]); a1[3] = fma2(p3, w.y, a1[3]);
                }
                if (tg0 >= 0) {
                    float v0[4], v1[4], v2[4], v3[4];
                    #pragma unroll
                    for (int t = 0; t < 4; ++t) {
                        upk(a0[t], v0[t], v1[t]);
                        upk(a1[t], v2[t], v3[t]);
                    }
                    float* r0 = res + (c0 + 0) * TTH + lt0;
                    float* r1 = res + (c0 + 1) * TTH + lt0;
                    float* r2 = res + (c0 + 2) * TTH + lt0;
                    float* r3 = res + (c0 + 3) * TTH + lt0;
                    float4 q0 = *(float4*)r0, q1 = *(float4*)r1,
                           q2 = *(float4*)r2, q3 = *(float4*)r3;
                    *(float4*)r0 = make_float4(q0.x + v0[0], q0.y + v0[1], q0.z + v0[2], q0.w + v0[3]);
                    *(float4*)r1 = make_float4(q1.x + v1[0], q1.y + v1[1], q1.z + v1[2], q1.w + v1[3]);
                    *(float4*)r2 = make_float4(q2.x + v2[0], q2.y + v2[1], q2.z + v2[2], q2.w + v2[3]);
                    *(float4*)r3 = make_float4(q3.x + v3[0], q3.y + v3[1], q3.z + v3[2], q3.w + v3[3]);
                }
            }
            __syncthreads();
        }
    }

    // ---- relu(skip) -> ybuf; stage end1 transposed [k][s] into wd ----
    for (int idx = tid; idx < 32 * TTH; idx += NTHREADS) {
        int ch = idx >> 9, lt = idx & (TTH - 1);
        int tg = tgb + lt;
        float xv = (tg >= 0 && tg < NT) ? x[b * NT + tg] : 0.f;
        ybuf[idx] = fmaxf(res[idx] - sw[ch] * xv, 0.f);
    }
    for (int j = tid; j < 8192; j += NTHREADS) {   // dest [k][s]: conflict-free STS
        int k = j >> 8, s = j & 255;
        wd[j] = end1_w[s * 32 + k];
    }
    __syncthreads();

    // ---- end head: chunks of 64 timesteps; ebuf[256][64] reuses res ----
    float* ebuf = res;
    const int s0 = (tid >> 4) * 4;   // 0..252 step 4
    const int t4 = (tid & 15) * 4;   // 0..60
    for (int chunk = 0; chunk < 8; ++chunk) {
        const int ltc = HALO + chunk * 64 + t4;
        const bool active = (ltc < TTH);    // chunk 7 partial
        u64 a0[4], a1[4];
        #pragma unroll
        for (int t = 0; t < 4; ++t) { a0[t] = 0ULL; a1[t] = 0ULL; }

        if (active) {  // E1: e = relu(end1 @ skip), channel-pair lanes
            #pragma unroll 2
            for (int k = 0; k < 32; ++k) {
                float4 yv = *(const float4*)(ybuf + k * TTH + ltc);
                u64 p0 = pk(yv.x, yv.x), p1 = pk(yv.y, yv.y),
                    p2 = pk(yv.z, yv.z), p3 = pk(yv.w, yv.w);
                ulonglong2 w = *(const ulonglong2*)(wd + k * 256 + s0);
                a0[0] = fma2(p0, w.x, a0[0]); a0[1] = fma2(p1, w.x, a0[1]);
                a0[2] = fma2(p2, w.x, a0[2]); a0[3] = fma2(p3, w.x, a0[3]);
                a1[0] = fma2(p0, w.y, a1[0]); a1[1] = fma2(p1, w.y, a1[1]);
                a1[2] = fma2(p2, w.y, a1[2]); a1[3] = fma2(p3, w.y, a1[3]);
            }
        }
        __syncthreads();   // prior chunk's E2 reads of ebuf complete
        if (active) {
            float v0[4], v1[4], v2[4], v3[4];
            #pragma unroll
            for (int t = 0; t < 4; ++t) {
                upk(a0[t], v0[t], v1[t]);
                upk(a1[t], v2[t], v3[t]);
            }
            *(float4*)(ebuf + (s0 + 0) * 64 + t4) =
                make_float4(fmaxf(v0[0],0.f), fmaxf(v0[1],0.f), fmaxf(v0[2],0.f), fmaxf(v0[3],0.f));
            *(float4*)(ebuf + (s0 + 1) * 64 + t4) =
                make_float4(fmaxf(v1[0],0.f), fmaxf(v1[1],0.f), fmaxf(v1[2],0.f), fmaxf(v1[3],0.f));
            *(float4*)(ebuf + (s0 + 2) * 64 + t4) =
                make_float4(fmaxf(v2[0],0.f), fmaxf(v2[1],0.f), fmaxf(v2[2],0.f), fmaxf(v2[3],0.f));
            *(float4*)(ebuf + (s0 + 3) * 64 + t4) =
                make_float4(fmaxf(v3[0],0.f), fmaxf(v3[1],0.f), fmaxf(v3[2],0.f), fmaxf(v3[3],0.f));
        }
        __syncthreads();   // e complete
        if (active) {  // E2: logit = end2 @ e, float4 k-major weight loads
            u64 acc2[4][2];
            #pragma unroll
            for (int a = 0; a < 4; ++a) { acc2[a][0] = 0ULL; acc2[a][1] = 0ULL; }
            #pragma unroll 2
            for (int k4 = 0; k4 < 64; ++k4) {
                ulonglong2 ev0 = *(const ulonglong2*)(ebuf + (k4 * 4 + 0) * 64 + t4);
                ulonglong2 ev1 = *(const ulonglong2*)(ebuf + (k4 * 4 + 1) * 64 + t4);
                ulonglong2 ev2 = *(const ulonglong2*)(ebuf + (k4 * 4 + 2) * 64 + t4);
                ulonglong2 ev3 = *(const ulonglong2*)(ebuf + (k4 * 4 + 3) * 64 + t4);
                #pragma unroll
                for (int cc = 0; cc < 4; ++cc) {
                    float4 w4 = __ldg((const float4*)(end2_w + (s0 + cc) * 256 + k4 * 4));
                    u64 wp0 = pk(w4.x, w4.x), wp1 = pk(w4.y, w4.y),
                        wp2 = pk(w4.z, w4.z), wp3 = pk(w4.w, w4.w);
                    acc2[cc][0] = fma2(ev0.x, wp0, acc2[cc][0]);
                    acc2[cc][1] = fma2(ev0.y, wp0, acc2[cc][1]);
                    acc2[cc][0] = fma2(ev1.x, wp1, acc2[cc][0]);
                    acc2[cc][1] = fma2(ev1.y, wp1, acc2[cc][1]);
                    acc2[cc][0] = fma2(ev2.x, wp2, acc2[cc][0]);
                    acc2[cc][1] = fma2(ev2.y, wp2, acc2[cc][1]);
                    acc2[cc][0] = fma2(ev3.x, wp3, acc2[cc][0]);
                    acc2[cc][1] = fma2(ev3.y, wp3, acc2[cc][1]);
                }
            }
            int tgc = tgb + ltc;
            #pragma unroll
            for (int cc = 0; cc < 4; ++cc) {
                float* op = out + ((size_t)(b * 256 + s0 + cc)) * NT + tgc;
                if (tgc + 4 <= NT) {
                    *(u64*)op       = acc2[cc][0];
                    *(u64*)(op + 2) = acc2[cc][1];
                } else {
                    #pragma unroll
                    for (int p = 0; p < 2; ++p) {
                        float a0_, a1_; upk(acc2[cc][p], a0_, a1_);
                        if (tgc + 2 * p     < NT) op[2 * p]     = a0_;
                        if (tgc + 2 * p + 1 < NT) op[2 * p + 1] = a1_;
                    }
                }
            }
        }
        __syncthreads();   // all E2 reads of ebuf done before next chunk overwrites
    }
}

extern "C" void kernel_launch(void* const* d_in, const int* in_sizes, int n_in,
                              void* d_out, int out_size) {
    const float* x       = (const float*)d_in[0];
    const float* h       = (const float*)d_in[1];
    const float* start_w = (const float*)d_in[2];
    const float* dil_w   = (const float*)d_in[3];
    const float* f_w     = (const float*)d_in[4];
    const float* g_w     = (const float*)d_in[5];
    const float* cf_w    = (const float*)d_in[6];
    const float* cg_w    = (const float*)d_in[7];
    const float* out_w   = (const float*)d_in[8];
    const float* end1_w  = (const float*)d_in[9];
    const float* end2_w  = (const float*)d_in[10];
    float* out = (float*)d_out;

    cudaFuncSetAttribute(wavenet_kernel,
                         cudaFuncAttributeMaxDynamicSharedMemorySize, SMEM_BYTES);
    wavenet_kernel<<<NB * TILES_PER_B, NTHREADS, SMEM_BYTES>>>(
        x, h, start_w, dil_w, f_w, g_w, cf_w, cg_w, out_w, end1_w, end2_w, out);
}